// round 14
// baseline (speedup 1.0000x reference)
#include <cuda_runtime.h>
#include <cuda.h>
#include <cuda_fp16.h>
#include <cstdint>
#include <cstring>

// ---------------- problem/tiling constants ----------------
#define B_DIM    16384
#define H_DIM    512
#define BM       128        // batch rows per CTA (M)
#define BN       256        // gate cols per CTA = 4 gates * 64 h (N)
#define BK       64         // K halfs per stage (128 bytes = SW128 atom)
#define NSTAGE   3
#define NKSTEP   16         // 1024 / BK
#define NTHREADS 256        // 8 warps: 2 along M x 4 along N, warp tile 64x64

// ---------------- fp16 scratch (device globals; no allocation) ----------------
__device__ __align__(128) __half g_x [B_DIM * 512];      // input fp16
__device__ __align__(128) __half g_h [B_DIM * 512];      // h_prev fp16
__device__ __align__(128) __half g_wx[2048 * 512];       // Wxh fp16
__device__ __align__(128) __half g_wh[2048 * 512];       // Whh fp16

// ---------------- smem layout (bytes) ----------------
#define OFF_FULL   0                        // 3 x 8B mbarriers (TMA full)
#define OFF_EMPTY  64                       // 3 x 8B mbarriers (slot empty)
#define OFF_BIAS   128                      // 256 floats
#define OFF_DATA   2048                     // 1024-aligned tile data
#define A_BYTES    (BM * 128)               // 16384
#define B_BYTES    (BN * 128)               // 32768
#define STAGE_BYTES (A_BYTES + B_BYTES)     // 49152
#define A_OFF(s)   (OFF_DATA + (s) * STAGE_BYTES)
#define B_OFF(s)   (A_OFF(s) + A_BYTES)
#define SMEM_TOTAL (OFF_DATA + NSTAGE * STAGE_BYTES)   // 149504 -> 1 CTA/SM
#define DST_LD     260                      // epilogue staging stride (floats)

// ---------------- PTX helpers ----------------
__device__ __forceinline__ uint32_t smem_u32(const void* p) {
    uint32_t a;
    asm("{ .reg .u64 t; cvta.to.shared.u64 t, %1; cvt.u32.u64 %0, t; }" : "=r"(a) : "l"(p));
    return a;
}

__device__ __forceinline__ uint32_t h2_as_u32(__half2 h) {
    uint32_t u;
    memcpy(&u, &h, 4);
    return u;
}

#define MBARRIER_INIT(addr, cnt) \
    asm volatile("mbarrier.init.shared.b64 [%0], %1;" :: "r"(addr), "r"((uint32_t)(cnt)) : "memory")

#define MBARRIER_ARRIVE(addr) \
    asm volatile("mbarrier.arrive.shared.b64 _, [%0];" :: "r"(addr) : "memory")

#define MBARRIER_EXPECT_TX(addr, bytes) \
    asm volatile("mbarrier.arrive.expect_tx.shared.b64 _, [%0], %1;" :: "r"(addr), "r"((uint32_t)(bytes)) : "memory")

#define MBARRIER_WAIT_PARITY(addr, parity) do {                                   \
    asm volatile(                                                                 \
        "{\n\t.reg .pred P;\n\t"                                                  \
        "WL_%=:\n\t"                                                              \
        "mbarrier.try_wait.parity.acquire.cta.shared::cta.b64 P, [%0], %1, 0x989680;\n\t" \
        "@P bra.uni WD_%=;\n\t"                                                   \
        "bra.uni WL_%=;\n\t"                                                      \
        "WD_%=:\n\t}"                                                             \
        :: "r"(addr), "r"((uint32_t)(parity)) : "memory");                        \
} while (0)

#define TMA_LOAD_2D(dst, map, c0, c1, mbar)                                        \
    asm volatile(                                                                  \
        "cp.async.bulk.tensor.2d.shared::cta.global.tile.mbarrier::complete_tx::bytes " \
        "[%0], [%1, {%2, %3}], [%4];"                                              \
        :: "r"((uint32_t)(dst)), "l"(map), "r"((int32_t)(c0)), "r"((int32_t)(c1)), \
           "r"((uint32_t)(mbar)) : "memory")

__device__ __forceinline__ void ldsm_x4(uint32_t* r, uint32_t addr) {
    asm volatile("ldmatrix.sync.aligned.m8n8.x4.shared.b16 {%0,%1,%2,%3}, [%4];"
                 : "=r"(r[0]), "=r"(r[1]), "=r"(r[2]), "=r"(r[3]) : "r"(addr));
}

__device__ __forceinline__ void mma_f16(float* d, const uint32_t* a, const uint32_t* b) {
    asm volatile(
        "mma.sync.aligned.m16n8k16.row.col.f32.f16.f16.f32 "
        "{%0,%1,%2,%3}, {%4,%5,%6,%7}, {%8,%9}, {%0,%1,%2,%3};"
        : "+f"(d[0]), "+f"(d[1]), "+f"(d[2]), "+f"(d[3])
        : "r"(a[0]), "r"(a[1]), "r"(a[2]), "r"(a[3]), "r"(b[0]), "r"(b[1]));
}

__device__ __forceinline__ float tanh_ap(float x) {
    float y; asm("tanh.approx.f32 %0, %1;" : "=f"(y) : "f"(x)); return y;
}

// ---------------- fused fp32 -> fp16 conversion (ALL arrays, one launch) ----------------
#define N4_BIG   (B_DIM * 512 / 4)
#define N4_W     (2048 * 512 / 4)
#define N4_TOTAL (2 * N4_BIG + 2 * N4_W)

__global__ void __launch_bounds__(256) f2h_all(const float* __restrict__ x,
                                               const float* __restrict__ h,
                                               const float* __restrict__ wx,
                                               const float* __restrict__ wh) {
    __half* const gx  = g_x;
    __half* const gh  = g_h;
    __half* const gwx = g_wx;
    __half* const gwh = g_wh;
    int stride = gridDim.x * blockDim.x;
    for (int i = blockIdx.x * blockDim.x + threadIdx.x; i < N4_TOTAL; i += stride) {
        const float* src;
        __half* dst;
        int j = i;
        if (j < N4_BIG)                  { src = x;  dst = gx; }
        else if ((j -= N4_BIG) < N4_BIG) { src = h;  dst = gh; }
        else if ((j -= N4_BIG) < N4_W)   { src = wx; dst = gwx; }
        else { j -= N4_W;                  src = wh; dst = gwh; }
        float4 v = ((const float4*)src)[j];
        uint2 o;
        o.x = h2_as_u32(__floats2half2_rn(v.x, v.y));
        o.y = h2_as_u32(__floats2half2_rn(v.z, v.w));
        ((uint2*)dst)[j] = o;
    }
}

// ---------------- TMA stage issue ----------------
__device__ __forceinline__ void issue_stage(uint32_t sb, int ks, int slot, int b0, int h0,
                                            const CUtensorMap* tmx, const CUtensorMap* tmh,
                                            const CUtensorMap* tmwx, const CUtensorMap* tmwh) {
    uint32_t fb = sb + OFF_FULL + 8 * slot;
    MBARRIER_EXPECT_TX(fb, STAGE_BYTES);
    int kk = ks * BK;
    const CUtensorMap* am = tmx;
    const CUtensorMap* wm = tmwx;
    int kb = kk;
    if (kk >= 512) { am = tmh; wm = tmwh; kb = kk - 512; }
    TMA_LOAD_2D(sb + A_OFF(slot), am, kb, b0, fb);
#pragma unroll
    for (int g = 0; g < 4; g++)
        TMA_LOAD_2D(sb + B_OFF(slot) + g * 8192, wm, kb, g * H_DIM + h0, fb);
}

// ---------------- main kernel ----------------
__global__ __launch_bounds__(NTHREADS, 1)
void slstm_mma(const __grid_constant__ CUtensorMap tmx,
               const __grid_constant__ CUtensorMap tmh,
               const __grid_constant__ CUtensorMap tmwx,
               const __grid_constant__ CUtensorMap tmwh,
               const float* __restrict__ c_prev,
               const float* __restrict__ m_prev,
               const float* __restrict__ n_prev,
               const float* __restrict__ bxh,
               const float* __restrict__ bhh,
               float* __restrict__ out)
{
    extern __shared__ __align__(1024) char smem[];
    const uint32_t sb = smem_u32(smem);
    const int tid  = threadIdx.x;
    const int warp = tid >> 5;
    const int lane = tid & 31;
    const int wm = warp & 1;          // M group (64 rows each)
    const int wn = warp >> 1;         // N group (64 cols each) == gate index
    const int g  = lane >> 2;
    const int h0 = blockIdx.x * 64;   // 64 h-values per CTA
    const int b0 = blockIdx.y * BM;
    // K-order stagger: decorrelate TMA bursts between neighboring CTAs
    const int koff = ((blockIdx.x ^ blockIdx.y) & 1) << 3;

    if (tid == 0) {
#pragma unroll
        for (int i = 0; i < NSTAGE; i++) {
            MBARRIER_INIT(sb + OFF_FULL + 8 * i, 1);
            MBARRIER_INIT(sb + OFF_EMPTY + 8 * i, 8);   // one arrive per warp
        }
    }
    {
        int j = (tid >> 6) * H_DIM + h0 + (tid & 63);
        ((float*)(smem + OFF_BIAS))[tid] = bxh[j] + bhh[j];
    }
    __syncthreads();

    if (tid == 0) {
#pragma unroll
        for (int s = 0; s < NSTAGE; s++)
            issue_stage(sb, (s + koff) & 15, s, b0, h0, &tmx, &tmh, &tmwx, &tmwh);
    }

    // ---- ldmatrix per-thread address constants (fp16, 128B rows, SW128) ----
    const uint32_t X    = (uint32_t)(lane & 7) << 4;
    const uint32_t hi16 = (uint32_t)(lane >> 4) << 4;
    const uint32_t rowA = (uint32_t)(wm * 64 + (lane & 15));
    const uint32_t rowB = (uint32_t)(wn * 64 + (lane & 15));

    float acc[4][8][4];
#pragma unroll
    for (int mi = 0; mi < 4; mi++)
#pragma unroll
        for (int j = 0; j < 8; j++)
#pragma unroll
            for (int e = 0; e < 4; e++) acc[mi][j][e] = 0.0f;

#pragma unroll
    for (int s = 0; s < NKSTEP; s++) {
        const int slot  = s % NSTAGE;          // compile-time under full unroll
        const int phase = (s / NSTAGE) & 1;
        MBARRIER_WAIT_PARITY(sb + OFF_FULL + 8 * slot, phase);

        const uint32_t Abase = sb + A_OFF(slot) + rowA * 128;   // + mi*2048
        const uint32_t Bbase = sb + B_OFF(slot) + rowB * 128;   // + j2*2048

#pragma unroll
        for (int k16 = 0; k16 < 4; k16++) {
            const uint32_t off = (((uint32_t)(k16 * 32)) | hi16) ^ X;

            uint32_t a[4][4];
#pragma unroll
            for (int mi = 0; mi < 4; mi++)
                ldsm_x4(a[mi], Abase + (uint32_t)mi * 2048 + off);

            uint32_t b[8][2];
#pragma unroll
            for (int j2 = 0; j2 < 4; j2++) {
                uint32_t r[4];
                ldsm_x4(r, Bbase + (uint32_t)j2 * 2048 + off);
                b[2 * j2][0]     = r[0];
                b[2 * j2][1]     = r[2];
                b[2 * j2 + 1][0] = r[1];
                b[2 * j2 + 1][1] = r[3];
            }

            // slot fully read after the last ldmatrix batch -> release early
            if (k16 == 3 && lane == 0)
                MBARRIER_ARRIVE(sb + OFF_EMPTY + 8 * slot);

#pragma unroll
            for (int mi = 0; mi < 4; mi++)
#pragma unroll
                for (int j = 0; j < 8; j++)
                    mma_f16(acc[mi][j], a[mi], b[j]);
        }

        // producer for this slot's refill = warp `slot` (0..2)
        if (s + NSTAGE < NKSTEP && warp == slot && lane == 0) {
            MBARRIER_WAIT_PARITY(sb + OFF_EMPTY + 8 * slot, phase);
            issue_stage(sb, (s + NSTAGE + koff) & 15, slot, b0, h0, &tmx, &tmh, &tmwx, &tmwh);
        }
    }

    __syncthreads();   // all warps done with pipeline smem

    // ---- stage accumulators to smem: Dst[128][DST_LD] (reuses pipeline smem) ----
    float* Dst = (float*)(smem + OFF_DATA);
    {
        const int r0 = wm * 64 + g;
        const int cb = wn * 64 + 2 * (lane & 3);
#pragma unroll
        for (int mi = 0; mi < 4; mi++)
#pragma unroll
            for (int j = 0; j < 8; j++) {
                int r = r0 + mi * 16;
                int c = cb + j * 8;
                *(float2*)(Dst + (size_t)r * DST_LD + c) =
                    make_float2(acc[mi][j][0], acc[mi][j][1]);
                *(float2*)(Dst + (size_t)(r + 8) * DST_LD + c) =
                    make_float2(acc[mi][j][2], acc[mi][j][3]);
            }
    }
    __syncthreads();

    // ---- fused elementwise epilogue: coalesced, fast transcendentals ----
    const float* bias = (const float*)(smem + OFF_BIAS);
    const size_t BH = (size_t)B_DIM * H_DIM;
#pragma unroll 4
    for (int e = 0; e < (BM * 64) / NTHREADS; e++) {
        int idx = tid + e * NTHREADS;
        int r = idx >> 6, hh = idx & 63;
        const float* drow = Dst + (size_t)r * DST_LD;
        float ig = drow[hh]       + bias[hh];
        float fg = drow[64 + hh]  + bias[64 + hh];
        float zg = drow[128 + hh] + bias[128 + hh];
        float og = drow[192 + hh] + bias[192 + hh];

        size_t gi = (size_t)(b0 + r) * H_DIM + h0 + hh;
        float cp = c_prev[gi], mp = m_prev[gi], np = n_prev[gi];

        float zt = tanh_ap(zg);
        float ot = 0.5f * tanh_ap(0.5f * og) + 0.5f;   // sigmoid
        float aa = fg + mp;
        float mt = fmaxf(aa, ig);
        float em = __expf(0.0f - fabsf(aa - ig));      // single exp
        float ft = (aa >= ig) ? 1.0f : em;
        float it = (aa >= ig) ? em : 1.0f;
        float ct = ft * cp + it * zt;
        float nt = ft * np + it;
        float ht = ot * __fdividef(ct, nt);

        out[gi]          = ht;
        out[BH + gi]     = ct;
        out[2 * BH + gi] = mt;
        out[3 * BH + gi] = nt;
    }
}

// ---------------- host side ----------------
typedef CUresult (*PFN_encodeTiled)(CUtensorMap*, CUtensorMapDataType, cuuint32_t, void*,
                                    const cuuint64_t*, const cuuint64_t*, const cuuint32_t*,
                                    const cuuint32_t*, CUtensorMapInterleave, CUtensorMapSwizzle,
                                    CUtensorMapL2promotion, CUtensorMapFloatOOBfill);

static PFN_encodeTiled get_encoder() {
    static PFN_encodeTiled fn = nullptr;
    if (!fn) {
        void* p = nullptr;
        cudaDriverEntryPointQueryResult st;
#if CUDART_VERSION >= 12050
        cudaGetDriverEntryPointByVersion("cuTensorMapEncodeTiled", &p, 12000, cudaEnableDefault, &st);
#else
        cudaGetDriverEntryPoint("cuTensorMapEncodeTiled", &p, cudaEnableDefault, &st);
#endif
        fn = (PFN_encodeTiled)p;
    }
    return fn;
}

static void make_map_h(CUtensorMap* m, const void* ptr, uint64_t d0, uint64_t d1,
                       uint32_t box0, uint32_t box1) {
    cuuint64_t dims[2]    = {d0, d1};
    cuuint64_t strides[1] = {d0 * 2};
    cuuint32_t box[2]     = {box0, box1};
    cuuint32_t es[2]      = {1, 1};
    get_encoder()(m, CU_TENSOR_MAP_DATA_TYPE_FLOAT16, 2, (void*)ptr, dims, strides, box, es,
                  CU_TENSOR_MAP_INTERLEAVE_NONE, CU_TENSOR_MAP_SWIZZLE_128B,
                  CU_TENSOR_MAP_L2_PROMOTION_L2_128B, CU_TENSOR_MAP_FLOAT_OOB_FILL_NONE);
}

extern "C" void kernel_launch(void* const* d_in, const int* in_sizes, int n_in,
                              void* d_out, int out_size)
{
    const float* input  = (const float*)d_in[0];
    const float* h_prev = (const float*)d_in[1];
    const float* c_prev = (const float*)d_in[2];
    const float* m_prev = (const float*)d_in[3];
    const float* n_prev = (const float*)d_in[4];
    const float* Wxh    = (const float*)d_in[5];
    const float* bxh    = (const float*)d_in[6];
    const float* Whh    = (const float*)d_in[7];
    const float* bhh    = (const float*)d_in[8];
    float* out = (float*)d_out;

    void *px, *ph, *pwx, *pwh;
    cudaGetSymbolAddress(&px,  g_x);
    cudaGetSymbolAddress(&ph,  g_h);
    cudaGetSymbolAddress(&pwx, g_wx);
    cudaGetSymbolAddress(&pwh, g_wh);

    // single fused fp32 -> fp16 conversion pass
    f2h_all<<<2048, 256>>>(input, h_prev, Wxh, Whh);

    CUtensorMap tmx, tmh, tmwx, tmwh;
    make_map_h(&tmx,  px,  512, (uint64_t)B_DIM, BK, BM);       // A: input fp16
    make_map_h(&tmh,  ph,  512, (uint64_t)B_DIM, BK, BM);       // A: h_prev fp16
    make_map_h(&tmwx, pwx, 512, 4 * (uint64_t)H_DIM, BK, 64);   // B: Wxh (per-gate 64-row box)
    make_map_h(&tmwh, pwh, 512, 4 * (uint64_t)H_DIM, BK, 64);   // B: Whh

    cudaFuncSetAttribute(slstm_mma, cudaFuncAttributeMaxDynamicSharedMemorySize, SMEM_TOTAL);

    dim3 grid(H_DIM / 64, B_DIM / BM);  // (8, 128) = 1024 CTAs, 1 per SM
    slstm_mma<<<grid, NTHREADS, SMEM_TOTAL>>>(tmx, tmh, tmwx, tmwh,
                                              c_prev, m_prev, n_prev, bxh, bhh, out);
}

// round 15
// speedup vs baseline: 1.3268x; 1.3268x over previous
#include <cuda_runtime.h>
#include <cuda.h>
#include <cuda_fp16.h>
#include <cstdint>
#include <cstring>

// ---------------- problem/tiling constants ----------------
#define B_DIM    16384
#define H_DIM    512
#define BM       128        // batch rows per CTA (M)
#define BN       128        // gate cols per CTA = 4 gates * 32 h (N)
#define BK       64         // K halfs per stage (128 bytes = SW128 atom)
#define NSTAGE   3
#define NKSTEP   16         // 1024 / BK
#define NTHREADS 256        // 8 warps: 4 along M x 2 along N, warp tile 32x64

// ---------------- fp16 scratch (device globals; no allocation) ----------------
__device__ __align__(128) __half g_x [B_DIM * 512];      // input fp16
__device__ __align__(128) __half g_h [B_DIM * 512];      // h_prev fp16
__device__ __align__(128) __half g_wx[2048 * 512];       // Wxh fp16
__device__ __align__(128) __half g_wh[2048 * 512];       // Whh fp16

// ---------------- smem layout (bytes) ----------------
#define OFF_FULL   0                        // 3 x 8B mbarriers (TMA full)
#define OFF_EMPTY  64                       // 3 x 8B mbarriers (slot empty)
#define OFF_BIAS   128                      // 128 floats
#define OFF_DATA   1024                     // 1024-aligned tile data
#define A_BYTES    (BM * 128)               // 16384
#define B_BYTES    (BN * 128)               // 16384
#define STAGE_BYTES (A_BYTES + B_BYTES)     // 32768
#define A_OFF(s)   (OFF_DATA + (s) * STAGE_BYTES)
#define B_OFF(s)   (A_OFF(s) + A_BYTES)
#define SMEM_TOTAL (OFF_DATA + NSTAGE * STAGE_BYTES)   // 99328 -> 2 CTAs/SM
#define DST_LD     132                      // epilogue staging stride (floats)

// ---------------- PTX helpers ----------------
__device__ __forceinline__ uint32_t smem_u32(const void* p) {
    uint32_t a;
    asm("{ .reg .u64 t; cvta.to.shared.u64 t, %1; cvt.u32.u64 %0, t; }" : "=r"(a) : "l"(p));
    return a;
}

__device__ __forceinline__ uint32_t h2_as_u32(__half2 h) {
    uint32_t u;
    memcpy(&u, &h, 4);
    return u;
}

#define MBARRIER_INIT(addr, cnt) \
    asm volatile("mbarrier.init.shared.b64 [%0], %1;" :: "r"(addr), "r"((uint32_t)(cnt)) : "memory")

#define MBARRIER_ARRIVE(addr) \
    asm volatile("mbarrier.arrive.shared.b64 _, [%0];" :: "r"(addr) : "memory")

#define MBARRIER_EXPECT_TX(addr, bytes) \
    asm volatile("mbarrier.arrive.expect_tx.shared.b64 _, [%0], %1;" :: "r"(addr), "r"((uint32_t)(bytes)) : "memory")

#define MBARRIER_WAIT_PARITY(addr, parity) do {                                   \
    asm volatile(                                                                 \
        "{\n\t.reg .pred P;\n\t"                                                  \
        "WL_%=:\n\t"                                                              \
        "mbarrier.try_wait.parity.acquire.cta.shared::cta.b64 P, [%0], %1, 0x989680;\n\t" \
        "@P bra.uni WD_%=;\n\t"                                                   \
        "bra.uni WL_%=;\n\t"                                                      \
        "WD_%=:\n\t}"                                                             \
        :: "r"(addr), "r"((uint32_t)(parity)) : "memory");                        \
} while (0)

#define TMA_LOAD_2D(dst, map, c0, c1, mbar)                                        \
    asm volatile(                                                                  \
        "cp.async.bulk.tensor.2d.shared::cta.global.tile.mbarrier::complete_tx::bytes " \
        "[%0], [%1, {%2, %3}], [%4];"                                              \
        :: "r"((uint32_t)(dst)), "l"(map), "r"((int32_t)(c0)), "r"((int32_t)(c1)), \
           "r"((uint32_t)(mbar)) : "memory")

__device__ __forceinline__ void ldsm_x4(uint32_t* r, uint32_t addr) {
    asm volatile("ldmatrix.sync.aligned.m8n8.x4.shared.b16 {%0,%1,%2,%3}, [%4];"
                 : "=r"(r[0]), "=r"(r[1]), "=r"(r[2]), "=r"(r[3]) : "r"(addr));
}

__device__ __forceinline__ void mma_f16(float* d, const uint32_t* a, const uint32_t* b) {
    asm volatile(
        "mma.sync.aligned.m16n8k16.row.col.f32.f16.f16.f32 "
        "{%0,%1,%2,%3}, {%4,%5,%6,%7}, {%8,%9}, {%0,%1,%2,%3};"
        : "+f"(d[0]), "+f"(d[1]), "+f"(d[2]), "+f"(d[3])
        : "r"(a[0]), "r"(a[1]), "r"(a[2]), "r"(a[3]), "r"(b[0]), "r"(b[1]));
}

__device__ __forceinline__ float tanh_ap(float x) {
    float y; asm("tanh.approx.f32 %0, %1;" : "=f"(y) : "f"(x)); return y;
}

__device__ __forceinline__ void prefetch_l2(const void* p) {
    asm volatile("prefetch.global.L2 [%0];" :: "l"(p));
}

// ---------------- fused fp32 -> fp16 conversion (ALL arrays, one launch) ----------------
#define N4_BIG   (B_DIM * 512 / 4)
#define N4_W     (2048 * 512 / 4)
#define N4_TOTAL (2 * N4_BIG + 2 * N4_W)

__global__ void __launch_bounds__(256) f2h_all(const float* __restrict__ x,
                                               const float* __restrict__ h,
                                               const float* __restrict__ wx,
                                               const float* __restrict__ wh) {
    __half* const gx  = g_x;
    __half* const gh  = g_h;
    __half* const gwx = g_wx;
    __half* const gwh = g_wh;
    int stride = gridDim.x * blockDim.x;
    for (int i = blockIdx.x * blockDim.x + threadIdx.x; i < N4_TOTAL; i += stride) {
        const float* src;
        __half* dst;
        int j = i;
        if (j < N4_BIG)                  { src = x;  dst = gx; }
        else if ((j -= N4_BIG) < N4_BIG) { src = h;  dst = gh; }
        else if ((j -= N4_BIG) < N4_W)   { src = wx; dst = gwx; }
        else { j -= N4_W;                  src = wh; dst = gwh; }
        float4 v = ((const float4*)src)[j];
        uint2 o;
        o.x = h2_as_u32(__floats2half2_rn(v.x, v.y));
        o.y = h2_as_u32(__floats2half2_rn(v.z, v.w));
        ((uint2*)dst)[j] = o;
    }
}

// ---------------- TMA stage issue ----------------
__device__ __forceinline__ void issue_stage(uint32_t sb, int ks, int slot, int b0, int h0,
                                            const CUtensorMap* tmx, const CUtensorMap* tmh,
                                            const CUtensorMap* tmwx, const CUtensorMap* tmwh) {
    uint32_t fb = sb + OFF_FULL + 8 * slot;
    MBARRIER_EXPECT_TX(fb, STAGE_BYTES);
    int kk = ks * BK;
    const CUtensorMap* am = tmx;
    const CUtensorMap* wm = tmwx;
    int kb = kk;
    if (kk >= 512) { am = tmh; wm = tmwh; kb = kk - 512; }
    TMA_LOAD_2D(sb + A_OFF(slot), am, kb, b0, fb);
#pragma unroll
    for (int g = 0; g < 4; g++)
        TMA_LOAD_2D(sb + B_OFF(slot) + g * 4096, wm, kb, g * H_DIM + h0, fb);
}

// ---------------- main kernel ----------------
__global__ __launch_bounds__(NTHREADS, 2)
void slstm_mma(const __grid_constant__ CUtensorMap tmx,
               const __grid_constant__ CUtensorMap tmh,
               const __grid_constant__ CUtensorMap tmwx,
               const __grid_constant__ CUtensorMap tmwh,
               const float* __restrict__ c_prev,
               const float* __restrict__ m_prev,
               const float* __restrict__ n_prev,
               const float* __restrict__ bxh,
               const float* __restrict__ bhh,
               float* __restrict__ out)
{
    extern __shared__ __align__(1024) char smem[];
    const uint32_t sb = smem_u32(smem);
    const int tid  = threadIdx.x;
    const int warp = tid >> 5;
    const int lane = tid & 31;
    const int wm = warp & 3;          // M group (32 rows each)
    const int wn = warp >> 2;         // N group (64 cols each)
    const int g  = lane >> 2;
    const int h0 = blockIdx.x * 32;   // 32 h-values per CTA
    const int b0 = blockIdx.y * BM;
    // K-order stagger: decorrelate chip-wide TMA bursts between neighbor CTAs
    const int koff = ((blockIdx.x ^ blockIdx.y) & 1) << 3;

    if (tid == 0) {
#pragma unroll
        for (int i = 0; i < NSTAGE; i++) {
            MBARRIER_INIT(sb + OFF_FULL + 8 * i, 1);
            MBARRIER_INIT(sb + OFF_EMPTY + 8 * i, 8);   // one arrive per warp
        }
    }
    if (tid < 128) {
        int j = (tid >> 5) * H_DIM + h0 + (tid & 31);
        ((float*)(smem + OFF_BIAS))[tid] = bxh[j] + bhh[j];
    }
    __syncthreads();

    if (tid == 0) {
#pragma unroll
        for (int s = 0; s < NSTAGE; s++)
            issue_stage(sb, (s + koff) & 15, s, b0, h0, &tmx, &tmh, &tmwx, &tmwh);
    }

    // ---- ldmatrix per-thread address constants (fp16, 128B rows, SW128) ----
    const uint32_t X    = (uint32_t)(lane & 7) << 4;
    const uint32_t hi16 = (uint32_t)(lane >> 4) << 4;
    const uint32_t rowA = (uint32_t)(wm * 32 + (lane & 15));
    const uint32_t rowB = (uint32_t)(wn * 64 + (lane & 15));

    float acc[2][8][4];
#pragma unroll
    for (int mi = 0; mi < 2; mi++)
#pragma unroll
        for (int j = 0; j < 8; j++)
#pragma unroll
            for (int e = 0; e < 4; e++) acc[mi][j][e] = 0.0f;

#pragma unroll
    for (int s = 0; s < NKSTEP; s++) {
        const int slot  = s % NSTAGE;          // compile-time under full unroll
        const int phase = (s / NSTAGE) & 1;
        MBARRIER_WAIT_PARITY(sb + OFF_FULL + 8 * slot, phase);

        const uint32_t Abase = sb + A_OFF(slot) + rowA * 128;   // + mi*2048
        const uint32_t Bbase = sb + B_OFF(slot) + rowB * 128;   // + j2*2048

#pragma unroll
        for (int k16 = 0; k16 < 4; k16++) {
            const uint32_t off = (((uint32_t)(k16 * 32)) | hi16) ^ X;

            uint32_t a[2][4];
#pragma unroll
            for (int mi = 0; mi < 2; mi++)
                ldsm_x4(a[mi], Abase + (uint32_t)mi * 2048 + off);

            uint32_t b[8][2];
#pragma unroll
            for (int j2 = 0; j2 < 4; j2++) {
                uint32_t r[4];
                ldsm_x4(r, Bbase + (uint32_t)j2 * 2048 + off);
                b[2 * j2][0]     = r[0];
                b[2 * j2][1]     = r[2];
                b[2 * j2 + 1][0] = r[1];
                b[2 * j2 + 1][1] = r[3];
            }

            // slot fully read after last ldmatrix -> release early for TMA refill
            if (k16 == 3 && lane == 0)
                MBARRIER_ARRIVE(sb + OFF_EMPTY + 8 * slot);

#pragma unroll
            for (int mi = 0; mi < 2; mi++)
#pragma unroll
                for (int j = 0; j < 8; j++)
                    mma_f16(acc[mi][j], a[mi], b[j]);
        }

        // producer for this slot's refill = warp `slot` (0..2)
        if (s + NSTAGE < NKSTEP && warp == slot && lane == 0) {
            MBARRIER_WAIT_PARITY(sb + OFF_EMPTY + 8 * slot, phase);
            issue_stage(sb, (s + NSTAGE + koff) & 15, slot, b0, h0, &tmx, &tmh, &tmwx, &tmwh);
        }

        // warm L2 for the epilogue's c/m/n tiles (one prefetch per 128B line)
        if (s == 10 && tid < 128) {
            size_t base = (size_t)(b0 + tid) * H_DIM + h0;   // 128B-aligned line
            prefetch_l2(c_prev + base);
            prefetch_l2(m_prev + base);
            prefetch_l2(n_prev + base);
        }
    }

    __syncthreads();   // all warps done with pipeline smem

    // ---- stage accumulators to smem: Dst[128][DST_LD] ----
    float* Dst = (float*)(smem + OFF_DATA);
    {
        const int r0 = wm * 32 + g;
        const int cb = wn * 64 + 2 * (lane & 3);
#pragma unroll
        for (int mi = 0; mi < 2; mi++)
#pragma unroll
            for (int j = 0; j < 8; j++) {
                int r = r0 + mi * 16;
                int c = cb + j * 8;
                *(float2*)(Dst + (size_t)r * DST_LD + c) =
                    make_float2(acc[mi][j][0], acc[mi][j][1]);
                *(float2*)(Dst + (size_t)(r + 8) * DST_LD + c) =
                    make_float2(acc[mi][j][2], acc[mi][j][3]);
            }
    }
    __syncthreads();

    // ---- fused elementwise epilogue: float2-vectorized, coalesced ----
    const float* bias = (const float*)(smem + OFF_BIAS);
    const size_t BH = (size_t)B_DIM * H_DIM;
#pragma unroll
    for (int e = 0; e < (BM * 32) / (NTHREADS * 2); e++) {
        int idx = tid + e * NTHREADS;
        int r  = idx >> 4;             // row 0..127
        int h2 = (idx & 15) * 2;       // even col 0..30
        const float* drow = Dst + (size_t)r * DST_LD;
        float2 ig2 = make_float2(drow[h2]      + bias[h2],      drow[h2 + 1]      + bias[h2 + 1]);
        float2 fg2 = make_float2(drow[32 + h2] + bias[32 + h2], drow[32 + h2 + 1] + bias[32 + h2 + 1]);
        float2 zg2 = make_float2(drow[64 + h2] + bias[64 + h2], drow[64 + h2 + 1] + bias[64 + h2 + 1]);
        float2 og2 = make_float2(drow[96 + h2] + bias[96 + h2], drow[96 + h2 + 1] + bias[96 + h2 + 1]);

        size_t gi = (size_t)(b0 + r) * H_DIM + h0 + h2;
        float2 cp2 = *(const float2*)(c_prev + gi);
        float2 mp2 = *(const float2*)(m_prev + gi);
        float2 np2 = *(const float2*)(n_prev + gi);

        float2 ht2, ct2, mt2, nt2;
        {
            float zt = tanh_ap(zg2.x);
            float ot = 0.5f * tanh_ap(0.5f * og2.x) + 0.5f;
            float aa = fg2.x + mp2.x;
            mt2.x = fmaxf(aa, ig2.x);
            float em = __expf(0.0f - fabsf(aa - ig2.x));
            float ft = (aa >= ig2.x) ? 1.0f : em;
            float it = (aa >= ig2.x) ? em : 1.0f;
            ct2.x = ft * cp2.x + it * zt;
            nt2.x = ft * np2.x + it;
            ht2.x = ot * __fdividef(ct2.x, nt2.x);
        }
        {
            float zt = tanh_ap(zg2.y);
            float ot = 0.5f * tanh_ap(0.5f * og2.y) + 0.5f;
            float aa = fg2.y + mp2.y;
            mt2.y = fmaxf(aa, ig2.y);
            float em = __expf(0.0f - fabsf(aa - ig2.y));
            float ft = (aa >= ig2.y) ? 1.0f : em;
            float it = (aa >= ig2.y) ? em : 1.0f;
            ct2.y = ft * cp2.y + it * zt;
            nt2.y = ft * np2.y + it;
            ht2.y = ot * __fdividef(ct2.y, nt2.y);
        }

        *(float2*)(out + gi)          = ht2;
        *(float2*)(out + BH + gi)     = ct2;
        *(float2*)(out + 2 * BH + gi) = mt2;
        *(float2*)(out + 3 * BH + gi) = nt2;
    }
}

// ---------------- host side ----------------
typedef CUresult (*PFN_encodeTiled)(CUtensorMap*, CUtensorMapDataType, cuuint32_t, void*,
                                    const cuuint64_t*, const cuuint64_t*, const cuuint32_t*,
                                    const cuuint32_t*, CUtensorMapInterleave, CUtensorMapSwizzle,
                                    CUtensorMapL2promotion, CUtensorMapFloatOOBfill);

static PFN_encodeTiled get_encoder() {
    static PFN_encodeTiled fn = nullptr;
    if (!fn) {
        void* p = nullptr;
        cudaDriverEntryPointQueryResult st;
#if CUDART_VERSION >= 12050
        cudaGetDriverEntryPointByVersion("cuTensorMapEncodeTiled", &p, 12000, cudaEnableDefault, &st);
#else
        cudaGetDriverEntryPoint("cuTensorMapEncodeTiled", &p, cudaEnableDefault, &st);
#endif
        fn = (PFN_encodeTiled)p;
    }
    return fn;
}

static void make_map_h(CUtensorMap* m, const void* ptr, uint64_t d0, uint64_t d1,
                       uint32_t box0, uint32_t box1) {
    cuuint64_t dims[2]    = {d0, d1};
    cuuint64_t strides[1] = {d0 * 2};
    cuuint32_t box[2]     = {box0, box1};
    cuuint32_t es[2]      = {1, 1};
    get_encoder()(m, CU_TENSOR_MAP_DATA_TYPE_FLOAT16, 2, (void*)ptr, dims, strides, box, es,
                  CU_TENSOR_MAP_INTERLEAVE_NONE, CU_TENSOR_MAP_SWIZZLE_128B,
                  CU_TENSOR_MAP_L2_PROMOTION_L2_128B, CU_TENSOR_MAP_FLOAT_OOB_FILL_NONE);
}

extern "C" void kernel_launch(void* const* d_in, const int* in_sizes, int n_in,
                              void* d_out, int out_size)
{
    const float* input  = (const float*)d_in[0];
    const float* h_prev = (const float*)d_in[1];
    const float* c_prev = (const float*)d_in[2];
    const float* m_prev = (const float*)d_in[3];
    const float* n_prev = (const float*)d_in[4];
    const float* Wxh    = (const float*)d_in[5];
    const float* bxh    = (const float*)d_in[6];
    const float* Whh    = (const float*)d_in[7];
    const float* bhh    = (const float*)d_in[8];
    float* out = (float*)d_out;

    void *px, *ph, *pwx, *pwh;
    cudaGetSymbolAddress(&px,  g_x);
    cudaGetSymbolAddress(&ph,  g_h);
    cudaGetSymbolAddress(&pwx, g_wx);
    cudaGetSymbolAddress(&pwh, g_wh);

    // single fused fp32 -> fp16 conversion pass
    f2h_all<<<2048, 256>>>(input, h_prev, Wxh, Whh);

    CUtensorMap tmx, tmh, tmwx, tmwh;
    make_map_h(&tmx,  px,  512, (uint64_t)B_DIM, BK, BM);       // A: input fp16
    make_map_h(&tmh,  ph,  512, (uint64_t)B_DIM, BK, BM);       // A: h_prev fp16
    make_map_h(&tmwx, pwx, 512, 4 * (uint64_t)H_DIM, BK, 32);   // B: Wxh (per-gate box)
    make_map_h(&tmwh, pwh, 512, 4 * (uint64_t)H_DIM, BK, 32);   // B: Whh

    cudaFuncSetAttribute(slstm_mma, cudaFuncAttributeMaxDynamicSharedMemorySize, SMEM_TOTAL);

    dim3 grid(H_DIM / 32, B_DIM / BM);  // (16, 128) = 2048 CTAs, 2 per SM
    slstm_mma<<<grid, NTHREADS, SMEM_TOTAL>>>(tmx, tmh, tmwx, tmwh,
                                              c_prev, m_prev, n_prev, bxh, bhh, out);
}

// round 16
// speedup vs baseline: 1.3535x; 1.0201x over previous
#include <cuda_runtime.h>
#include <cuda.h>
#include <cuda_fp16.h>
#include <cstdint>
#include <cstring>

// ---------------- problem/tiling constants ----------------
#define B_DIM    16384
#define H_DIM    512
#define BM       128        // batch rows per CTA (M)
#define BN       128        // gate cols per CTA = 4 gates * 32 h (N)
#define BK       64         // K halfs per stage (128 bytes = SW128 atom)
#define NSTAGE   3
#define NKSTEP   16         // 1024 / BK
#define NTHREADS 256        // 8 warps: 4 along M x 2 along N, warp tile 32x64

// ---------------- fp16 scratch (device globals; no allocation) ----------------
__device__ __align__(128) __half g_x [B_DIM * 512];      // input fp16
__device__ __align__(128) __half g_h [B_DIM * 512];      // h_prev fp16
__device__ __align__(128) __half g_wx[2048 * 512];       // Wxh fp16
__device__ __align__(128) __half g_wh[2048 * 512];       // Whh fp16

// ---------------- smem layout (bytes) ----------------
// mbarriers spread to distinct 128B lines to reduce polling contention
#define OFF_FULL(i)  ((i) * 128)            // full[i]  at 0,128,256
#define OFF_EMPTY(i) (384 + (i) * 128)      // empty[i] at 384,512,640
#define OFF_BIAS   768                      // 128 floats (768..1280)
#define OFF_DATA   2048                     // 1024-aligned tile data
#define A_BYTES    (BM * 128)               // 16384
#define B_BYTES    (BN * 128)               // 16384
#define STAGE_BYTES (A_BYTES + B_BYTES)     // 32768
#define A_OFF(s)   (OFF_DATA + (s) * STAGE_BYTES)
#define B_OFF(s)   (A_OFF(s) + A_BYTES)
#define SMEM_TOTAL (OFF_DATA + NSTAGE * STAGE_BYTES)   // 100352 -> 2 CTAs/SM
#define DST_LD     132                      // epilogue staging stride (floats)

// ---------------- PTX helpers ----------------
__device__ __forceinline__ uint32_t smem_u32(const void* p) {
    uint32_t a;
    asm("{ .reg .u64 t; cvta.to.shared.u64 t, %1; cvt.u32.u64 %0, t; }" : "=r"(a) : "l"(p));
    return a;
}

__device__ __forceinline__ uint32_t h2_as_u32(__half2 h) {
    uint32_t u;
    memcpy(&u, &h, 4);
    return u;
}

#define MBARRIER_INIT(addr, cnt) \
    asm volatile("mbarrier.init.shared.b64 [%0], %1;" :: "r"(addr), "r"((uint32_t)(cnt)) : "memory")

#define MBARRIER_ARRIVE(addr) \
    asm volatile("mbarrier.arrive.shared.b64 _, [%0];" :: "r"(addr) : "memory")

#define MBARRIER_EXPECT_TX(addr, bytes) \
    asm volatile("mbarrier.arrive.expect_tx.shared.b64 _, [%0], %1;" :: "r"(addr), "r"((uint32_t)(bytes)) : "memory")

#define MBARRIER_WAIT_PARITY(addr, parity) do {                                   \
    asm volatile(                                                                 \
        "{\n\t.reg .pred P;\n\t"                                                  \
        "WL_%=:\n\t"                                                              \
        "mbarrier.try_wait.parity.acquire.cta.shared::cta.b64 P, [%0], %1, 0x989680;\n\t" \
        "@P bra.uni WD_%=;\n\t"                                                   \
        "bra.uni WL_%=;\n\t"                                                      \
        "WD_%=:\n\t}"                                                             \
        :: "r"(addr), "r"((uint32_t)(parity)) : "memory");                        \
} while (0)

#define TMA_LOAD_2D(dst, map, c0, c1, mbar)                                        \
    asm volatile(                                                                  \
        "cp.async.bulk.tensor.2d.shared::cta.global.tile.mbarrier::complete_tx::bytes " \
        "[%0], [%1, {%2, %3}], [%4];"                                              \
        :: "r"((uint32_t)(dst)), "l"(map), "r"((int32_t)(c0)), "r"((int32_t)(c1)), \
           "r"((uint32_t)(mbar)) : "memory")

#define TMA_LOAD_3D(dst, map, c0, c1, c2, mbar)                                    \
    asm volatile(                                                                  \
        "cp.async.bulk.tensor.3d.shared::cta.global.tile.mbarrier::complete_tx::bytes " \
        "[%0], [%1, {%2, %3, %4}], [%5];"                                          \
        :: "r"((uint32_t)(dst)), "l"(map), "r"((int32_t)(c0)), "r"((int32_t)(c1)), \
           "r"((int32_t)(c2)), "r"((uint32_t)(mbar)) : "memory")

__device__ __forceinline__ void ldsm_x4(uint32_t* r, uint32_t addr) {
    asm volatile("ldmatrix.sync.aligned.m8n8.x4.shared.b16 {%0,%1,%2,%3}, [%4];"
                 : "=r"(r[0]), "=r"(r[1]), "=r"(r[2]), "=r"(r[3]) : "r"(addr));
}

__device__ __forceinline__ void mma_f16(float* d, const uint32_t* a, const uint32_t* b) {
    asm volatile(
        "mma.sync.aligned.m16n8k16.row.col.f32.f16.f16.f32 "
        "{%0,%1,%2,%3}, {%4,%5,%6,%7}, {%8,%9}, {%0,%1,%2,%3};"
        : "+f"(d[0]), "+f"(d[1]), "+f"(d[2]), "+f"(d[3])
        : "r"(a[0]), "r"(a[1]), "r"(a[2]), "r"(a[3]), "r"(b[0]), "r"(b[1]));
}

__device__ __forceinline__ float tanh_ap(float x) {
    float y; asm("tanh.approx.f32 %0, %1;" : "=f"(y) : "f"(x)); return y;
}

__device__ __forceinline__ void prefetch_l2(const void* p) {
    asm volatile("prefetch.global.L2 [%0];" :: "l"(p));
}

// ---------------- fused fp32 -> fp16 conversion (ALL arrays, one launch) ----------------
#define N4_BIG   (B_DIM * 512 / 4)
#define N4_W     (2048 * 512 / 4)
#define N4_TOTAL (2 * N4_BIG + 2 * N4_W)

__global__ void __launch_bounds__(256) f2h_all(const float* __restrict__ x,
                                               const float* __restrict__ h,
                                               const float* __restrict__ wx,
                                               const float* __restrict__ wh) {
    __half* const gx  = g_x;
    __half* const gh  = g_h;
    __half* const gwx = g_wx;
    __half* const gwh = g_wh;
    int stride = gridDim.x * blockDim.x;
    for (int i = blockIdx.x * blockDim.x + threadIdx.x; i < N4_TOTAL; i += stride) {
        const float* src;
        __half* dst;
        int j = i;
        if (j < N4_BIG)                  { src = x;  dst = gx; }
        else if ((j -= N4_BIG) < N4_BIG) { src = h;  dst = gh; }
        else if ((j -= N4_BIG) < N4_W)   { src = wx; dst = gwx; }
        else { j -= N4_W;                  src = wh; dst = gwh; }
        float4 v = ((const float4*)src)[j];
        uint2 o;
        o.x = h2_as_u32(__floats2half2_rn(v.x, v.y));
        o.y = h2_as_u32(__floats2half2_rn(v.z, v.w));
        ((uint2*)dst)[j] = o;
    }
}

// ---------------- TMA stage issue (A: 2D, B: one 3D covering all 4 gates) ----------------
__device__ __forceinline__ void issue_stage(uint32_t sb, int ks, int slot, int b0, int h0,
                                            const CUtensorMap* tmx, const CUtensorMap* tmh,
                                            const CUtensorMap* tmwx, const CUtensorMap* tmwh) {
    uint32_t fb = sb + OFF_FULL(slot);
    MBARRIER_EXPECT_TX(fb, STAGE_BYTES);
    int kk = ks * BK;
    const CUtensorMap* am = tmx;
    const CUtensorMap* wm = tmwx;
    int kb = kk;
    if (kk >= 512) { am = tmh; wm = tmwh; kb = kk - 512; }
    TMA_LOAD_2D(sb + A_OFF(slot), am, kb, b0, fb);
    TMA_LOAD_3D(sb + B_OFF(slot), wm, kb, h0, 0, fb);   // (k, h, gate) box (64,32,4)
}

// ---------------- main kernel ----------------
__global__ __launch_bounds__(NTHREADS, 2)
void slstm_mma(const __grid_constant__ CUtensorMap tmx,
               const __grid_constant__ CUtensorMap tmh,
               const __grid_constant__ CUtensorMap tmwx,
               const __grid_constant__ CUtensorMap tmwh,
               const float* __restrict__ c_prev,
               const float* __restrict__ m_prev,
               const float* __restrict__ n_prev,
               const float* __restrict__ bxh,
               const float* __restrict__ bhh,
               float* __restrict__ out)
{
    extern __shared__ __align__(1024) char smem[];
    const uint32_t sb = smem_u32(smem);
    const int tid  = threadIdx.x;
    const int warp = tid >> 5;
    const int lane = tid & 31;
    const int wm = warp & 3;          // M group (32 rows each)
    const int wn = warp >> 2;         // N group (64 cols each)
    const int g  = lane >> 2;
    const int h0 = blockIdx.x * 32;   // 32 h-values per CTA
    const int b0 = blockIdx.y * BM;
    // K-order stagger: decorrelate chip-wide TMA bursts between neighbor CTAs
    const int koff = ((blockIdx.x ^ blockIdx.y) & 1) << 3;

    if (tid == 0) {
#pragma unroll
        for (int i = 0; i < NSTAGE; i++) {
            MBARRIER_INIT(sb + OFF_FULL(i), 1);
            MBARRIER_INIT(sb + OFF_EMPTY(i), 8);   // one arrive per warp
        }
    }
    if (tid < 128) {
        int j = (tid >> 5) * H_DIM + h0 + (tid & 31);
        ((float*)(smem + OFF_BIAS))[tid] = bxh[j] + bhh[j];
    }
    __syncthreads();

    if (tid == 0) {
#pragma unroll
        for (int s = 0; s < NSTAGE; s++)
            issue_stage(sb, (s + koff) & 15, s, b0, h0, &tmx, &tmh, &tmwx, &tmwh);
    }

    // ---- ldmatrix per-thread address constants (fp16, 128B rows, SW128) ----
    const uint32_t X    = (uint32_t)(lane & 7) << 4;
    const uint32_t hi16 = (uint32_t)(lane >> 4) << 4;
    const uint32_t rowA = (uint32_t)(wm * 32 + (lane & 15));
    const uint32_t rowB = (uint32_t)(wn * 64 + (lane & 15));

    float acc[2][8][4];
#pragma unroll
    for (int mi = 0; mi < 2; mi++)
#pragma unroll
        for (int j = 0; j < 8; j++)
#pragma unroll
            for (int e = 0; e < 4; e++) acc[mi][j][e] = 0.0f;

#pragma unroll
    for (int s = 0; s < NKSTEP; s++) {
        const int slot  = s % NSTAGE;          // compile-time under full unroll
        const int phase = (s / NSTAGE) & 1;
        MBARRIER_WAIT_PARITY(sb + OFF_FULL(slot), phase);

        const uint32_t Abase = sb + A_OFF(slot) + rowA * 128;   // + mi*2048
        const uint32_t Bbase = sb + B_OFF(slot) + rowB * 128;   // + j2*2048

#pragma unroll
        for (int k16 = 0; k16 < 4; k16++) {
            const uint32_t off = (((uint32_t)(k16 * 32)) | hi16) ^ X;

            uint32_t a[2][4];
#pragma unroll
            for (int mi = 0; mi < 2; mi++)
                ldsm_x4(a[mi], Abase + (uint32_t)mi * 2048 + off);

            uint32_t b[8][2];
#pragma unroll
            for (int j2 = 0; j2 < 4; j2++) {
                uint32_t r[4];
                ldsm_x4(r, Bbase + (uint32_t)j2 * 2048 + off);
                b[2 * j2][0]     = r[0];
                b[2 * j2][1]     = r[2];
                b[2 * j2 + 1][0] = r[1];
                b[2 * j2 + 1][1] = r[3];
            }

            // slot fully read after last ldmatrix -> release early for TMA refill
            if (k16 == 3 && lane == 0)
                MBARRIER_ARRIVE(sb + OFF_EMPTY(slot));

#pragma unroll
            for (int mi = 0; mi < 2; mi++)
#pragma unroll
                for (int j = 0; j < 8; j++)
                    mma_f16(acc[mi][j], a[mi], b[j]);
        }

        // producer for this slot's refill = warp `slot` (0..2)
        if (s + NSTAGE < NKSTEP && warp == slot && lane == 0) {
            MBARRIER_WAIT_PARITY(sb + OFF_EMPTY(slot), phase);
            issue_stage(sb, (s + NSTAGE + koff) & 15, slot, b0, h0, &tmx, &tmh, &tmwx, &tmwh);
        }

        // warm L2 for the epilogue's c/m/n tiles (one prefetch per 128B line)
        if (s == 8 && tid < 128) {
            size_t base = (size_t)(b0 + tid) * H_DIM + h0;   // 128B-aligned line
            prefetch_l2(c_prev + base);
            prefetch_l2(m_prev + base);
            prefetch_l2(n_prev + base);
        }
    }

    __syncthreads();   // all warps done with pipeline smem

    // ---- stage accumulators to smem: Dst[128][DST_LD] ----
    float* Dst = (float*)(smem + OFF_DATA);
    {
        const int r0 = wm * 32 + g;
        const int cb = wn * 64 + 2 * (lane & 3);
#pragma unroll
        for (int mi = 0; mi < 2; mi++)
#pragma unroll
            for (int j = 0; j < 8; j++) {
                int r = r0 + mi * 16;
                int c = cb + j * 8;
                *(float2*)(Dst + (size_t)r * DST_LD + c) =
                    make_float2(acc[mi][j][0], acc[mi][j][1]);
                *(float2*)(Dst + (size_t)(r + 8) * DST_LD + c) =
                    make_float2(acc[mi][j][2], acc[mi][j][3]);
            }
    }
    __syncthreads();

    // ---- fused elementwise epilogue: float2-vectorized, coalesced ----
    const float* bias = (const float*)(smem + OFF_BIAS);
    const size_t BH = (size_t)B_DIM * H_DIM;
#pragma unroll
    for (int e = 0; e < (BM * 32) / (NTHREADS * 2); e++) {
        int idx = tid + e * NTHREADS;
        int r  = idx >> 4;             // row 0..127
        int h2 = (idx & 15) * 2;       // even col 0..30
        const float* drow = Dst + (size_t)r * DST_LD;
        float2 ig2 = make_float2(drow[h2]      + bias[h2],      drow[h2 + 1]      + bias[h2 + 1]);
        float2 fg2 = make_float2(drow[32 + h2] + bias[32 + h2], drow[32 + h2 + 1] + bias[32 + h2 + 1]);
        float2 zg2 = make_float2(drow[64 + h2] + bias[64 + h2], drow[64 + h2 + 1] + bias[64 + h2 + 1]);
        float2 og2 = make_float2(drow[96 + h2] + bias[96 + h2], drow[96 + h2 + 1] + bias[96 + h2 + 1]);

        size_t gi = (size_t)(b0 + r) * H_DIM + h0 + h2;
        float2 cp2 = *(const float2*)(c_prev + gi);
        float2 mp2 = *(const float2*)(m_prev + gi);
        float2 np2 = *(const float2*)(n_prev + gi);

        float2 ht2, ct2, mt2, nt2;
        {
            float zt = tanh_ap(zg2.x);
            float ot = 0.5f * tanh_ap(0.5f * og2.x) + 0.5f;
            float aa = fg2.x + mp2.x;
            mt2.x = fmaxf(aa, ig2.x);
            float em = __expf(0.0f - fabsf(aa - ig2.x));
            float ft = (aa >= ig2.x) ? 1.0f : em;
            float it = (aa >= ig2.x) ? em : 1.0f;
            ct2.x = ft * cp2.x + it * zt;
            nt2.x = ft * np2.x + it;
            ht2.x = ot * __fdividef(ct2.x, nt2.x);
        }
        {
            float zt = tanh_ap(zg2.y);
            float ot = 0.5f * tanh_ap(0.5f * og2.y) + 0.5f;
            float aa = fg2.y + mp2.y;
            mt2.y = fmaxf(aa, ig2.y);
            float em = __expf(0.0f - fabsf(aa - ig2.y));
            float ft = (aa >= ig2.y) ? 1.0f : em;
            float it = (aa >= ig2.y) ? em : 1.0f;
            ct2.y = ft * cp2.y + it * zt;
            nt2.y = ft * np2.y + it;
            ht2.y = ot * __fdividef(ct2.y, nt2.y);
        }

        *(float2*)(out + gi)          = ht2;
        *(float2*)(out + BH + gi)     = ct2;
        *(float2*)(out + 2 * BH + gi) = mt2;
        *(float2*)(out + 3 * BH + gi) = nt2;
    }
}

// ---------------- host side ----------------
typedef CUresult (*PFN_encodeTiled)(CUtensorMap*, CUtensorMapDataType, cuuint32_t, void*,
                                    const cuuint64_t*, const cuuint64_t*, const cuuint32_t*,
                                    const cuuint32_t*, CUtensorMapInterleave, CUtensorMapSwizzle,
                                    CUtensorMapL2promotion, CUtensorMapFloatOOBfill);

static PFN_encodeTiled get_encoder() {
    static PFN_encodeTiled fn = nullptr;
    if (!fn) {
        void* p = nullptr;
        cudaDriverEntryPointQueryResult st;
#if CUDART_VERSION >= 12050
        cudaGetDriverEntryPointByVersion("cuTensorMapEncodeTiled", &p, 12000, cudaEnableDefault, &st);
#else
        cudaGetDriverEntryPoint("cuTensorMapEncodeTiled", &p, cudaEnableDefault, &st);
#endif
        fn = (PFN_encodeTiled)p;
    }
    return fn;
}

static void make_map_h(CUtensorMap* m, const void* ptr, uint64_t d0, uint64_t d1,
                       uint32_t box0, uint32_t box1) {
    cuuint64_t dims[2]    = {d0, d1};
    cuuint64_t strides[1] = {d0 * 2};
    cuuint32_t box[2]     = {box0, box1};
    cuuint32_t es[2]      = {1, 1};
    get_encoder()(m, CU_TENSOR_MAP_DATA_TYPE_FLOAT16, 2, (void*)ptr, dims, strides, box, es,
                  CU_TENSOR_MAP_INTERLEAVE_NONE, CU_TENSOR_MAP_SWIZZLE_128B,
                  CU_TENSOR_MAP_L2_PROMOTION_L2_128B, CU_TENSOR_MAP_FLOAT_OOB_FILL_NONE);
}

// 3D weight map: (k=512, h=512, gate=4), box (BK, 32, 4)
static void make_map_w3(CUtensorMap* m, const void* ptr) {
    cuuint64_t dims[3]    = {512, 512, 4};
    cuuint64_t strides[2] = {512 * 2, (cuuint64_t)512 * 512 * 2};
    cuuint32_t box[3]     = {BK, 32, 4};
    cuuint32_t es[3]      = {1, 1, 1};
    get_encoder()(m, CU_TENSOR_MAP_DATA_TYPE_FLOAT16, 3, (void*)ptr, dims, strides, box, es,
                  CU_TENSOR_MAP_INTERLEAVE_NONE, CU_TENSOR_MAP_SWIZZLE_128B,
                  CU_TENSOR_MAP_L2_PROMOTION_L2_128B, CU_TENSOR_MAP_FLOAT_OOB_FILL_NONE);
}

extern "C" void kernel_launch(void* const* d_in, const int* in_sizes, int n_in,
                              void* d_out, int out_size)
{
    const float* input  = (const float*)d_in[0];
    const float* h_prev = (const float*)d_in[1];
    const float* c_prev = (const float*)d_in[2];
    const float* m_prev = (const float*)d_in[3];
    const float* n_prev = (const float*)d_in[4];
    const float* Wxh    = (const float*)d_in[5];
    const float* bxh    = (const float*)d_in[6];
    const float* Whh    = (const float*)d_in[7];
    const float* bhh    = (const float*)d_in[8];
    float* out = (float*)d_out;

    void *px, *ph, *pwx, *pwh;
    cudaGetSymbolAddress(&px,  g_x);
    cudaGetSymbolAddress(&ph,  g_h);
    cudaGetSymbolAddress(&pwx, g_wx);
    cudaGetSymbolAddress(&pwh, g_wh);

    // single fused fp32 -> fp16 conversion pass
    f2h_all<<<2048, 256>>>(input, h_prev, Wxh, Whh);

    CUtensorMap tmx, tmh, tmwx, tmwh;
    make_map_h(&tmx, px, 512, (uint64_t)B_DIM, BK, BM);   // A: input fp16
    make_map_h(&tmh, ph, 512, (uint64_t)B_DIM, BK, BM);   // A: h_prev fp16
    make_map_w3(&tmwx, pwx);                              // B: Wxh 3D (k,h,gate)
    make_map_w3(&tmwh, pwh);                              // B: Whh 3D

    cudaFuncSetAttribute(slstm_mma, cudaFuncAttributeMaxDynamicSharedMemorySize, SMEM_TOTAL);

    dim3 grid(H_DIM / 32, B_DIM / BM);  // (16, 128) = 2048 CTAs, 2 per SM
    slstm_mma<<<grid, NTHREADS, SMEM_TOTAL>>>(tmx, tmh, tmwx, tmwh,
                                              c_prev, m_prev, n_prev, bxh, bhh, out);
}